// round 16
// baseline (speedup 1.0000x reference)
#include <cuda_runtime.h>
#include <cstdint>
#include <math.h>

#define CC    96
#define HH    256
#define WWL   256
#define HW    (HH * WWL)
#define NWIN  2048
#define NT    512
#define GRID  148
#define XPITCH 264        // window channel pitch (floats): %32 == 8

// dynamic smem (floats): WrP [6][12][32][4] = 9216 ; WiP = 9216 ; XW [96][264] = 25344
#define WRP_F 0
#define WIP_F 9216
#define XW_F  18432
#define SMEM_DYN ((18432 + CC * XPITCH) * 4)     // 175104 B

// ---------------------------------------------------------------------------
__device__ __forceinline__ uint32_t tf32r(float f) {
    uint32_t u;
    asm("cvt.rna.tf32.f32 %0, %1;" : "=r"(u) : "f"(f));
    return u;
}
__device__ __forceinline__ void mma8(float* d, const uint32_t* a, const uint32_t* b) {
    asm volatile(
        "mma.sync.aligned.m16n8k8.row.col.f32.tf32.tf32.f32 "
        "{%0,%1,%2,%3}, {%4,%5,%6,%7}, {%8,%9}, {%0,%1,%2,%3};"
        : "+f"(d[0]), "+f"(d[1]), "+f"(d[2]), "+f"(d[3])
        : "r"(a[0]), "r"(a[1]), "r"(a[2]), "r"(a[3]), "r"(b[0]), "r"(b[1]));
}
__device__ __forceinline__ void decode_rq(int r, int& p, int& q) {
    if (r < 112) { p = 1 + (r >> 4); q = r & 15; }
    else { int r2 = r - 112; if (r2 < 9) { p = 0; q = r2; } else { p = 8; q = r2 - 9; } }
}

// ---------------------------------------------------------------------------
__global__ void __launch_bounds__(NT, 1)
fused_kernel(const float* __restrict__ x,
             const float* __restrict__ w_real, const float* __restrict__ b_real,
             const float* __restrict__ w_imag, const float* __restrict__ b_imag,
             const float* __restrict__ car_w1, const float* __restrict__ car_b1,
             const float* __restrict__ car_w2, const float* __restrict__ car_b2,
             const float* __restrict__ cai_w1, const float* __restrict__ cai_b1,
             const float* __restrict__ cai_w2, const float* __restrict__ cai_b2,
             float* __restrict__ out)
{
    extern __shared__ float smf[];
    float* WrP = smf + WRP_F;
    float* WiP = smf + WIP_F;
    float* XW  = smf + XW_F;

    __shared__ float s_pool[CC], s_hid[32], s_ar[CC], s_ai[CC];

    const int t    = threadIdx.x;
    const int wid  = t >> 5;
    const int lane = t & 31;
    const int g    = lane >> 2;
    const int fid  = lane & 3;

    // ---- one-time: W matrices -> fragment-permuted tf32 A-tiles ----
    for (int idx = t; idx < 9216; idx += NT) {
        int mt = idx / 1536;
        int rem = idx - mt * 1536;
        int ks = rem >> 7;
        int l  = (rem >> 2) & 31;
        int j  = rem & 3;
        int row = 16 * mt + (l >> 2) + 8 * (j & 1);
        int col = 8 * ks + (l & 3) + 4 * (j >> 1);
        WrP[idx] = __uint_as_float(tf32r(w_real[row * CC + col]));
        WiP[idx] = __uint_as_float(tf32r(w_imag[row * CC + col]));
    }

    // ---- one-time: imag attention (pool == b_imag exactly) ----
    if (t < 64) {
        int c = t >> 1, p = t & 1;
        const float* w1 = cai_w1 + c * CC + p * 48;
        float s = 0.f;
        #pragma unroll 8
        for (int k = 0; k < 48; k++) s += w1[k] * b_imag[p * 48 + k];
        s += __shfl_xor_sync(0xffffffffu, s, 1);
        if (!(t & 1)) s_hid[c] = fmaxf(s + cai_b1[c], 0.f);
    }
    __syncthreads();
    if (t < CC) {
        float s = cai_b2[t];
        const float* w2 = cai_w2 + t * 32;
        #pragma unroll
        for (int j = 0; j < 32; j++) s += w2[j] * s_hid[j];
        s_ai[t] = 1.f + 1.f / (1.f + expf(-s));
    }

    // ---- per-warp MMA geometry ----
    const int wm    = wid & 1;                    // m half (3 mt tiles)
    const int wn    = wid >> 1;                   // n group 0..7
    const int nbase = 2 * wn + ((wn > 6) ? 1 : 0);   // {0,2,4,6,8,10,12,15}
    const int cnt   = (wn >= 6) ? 3 : 2;          // 18 real n-tiles total

    int paddr[3];
    #pragma unroll
    for (int s = 0; s < 3; s++) {
        int r = 8 * (nbase + s) + g;
        int p, q; decode_rq(r, p, q);
        int p2 = (16 - p) & 15, q2 = (16 - q) & 15;
        paddr[s] = (p * 16 + q) | ((p2 * 16 + q2) << 16);
    }

    // ================= persistent window loop =================
    for (int win = blockIdx.x; win < NWIN; win += GRID) {
        const int b  = win >> 8;
        const int h0 = ((win >> 4) & 15) << 4;
        const int w0 = (win & 15) << 4;
        const float* xb = x + (size_t)b * CC * HW;
        float* ob = out + (size_t)b * CC * HW;

        __syncthreads();   // prior MMA reads of XW + epilogue reads of s_ar done

        // ---- stage raw window: coalesced float4 loads ----
        for (int idx = t; idx < CC * 64; idx += NT) {
            int k = idx >> 6, f = idx & 63;
            int p = f >> 2, qg = (f & 3) << 2;
            float4 v = *(const float4*)(xb + (size_t)k * HW
                                        + (size_t)(h0 + p) * WWL + w0 + qg);
            *(float4*)(XW + k * XPITCH + p * 16 + qg) = v;
        }
        __syncthreads();

        // ---- real attention (pool from window corner) ----
        if (t < 192) {
            int c = t >> 1, p = t & 1;
            const float* wr = w_real + c * CC + p * 48;
            float s = 0.f;
            #pragma unroll 8
            for (int k = 0; k < 48; k++) s += wr[k] * XW[(p * 48 + k) * XPITCH];
            s += __shfl_xor_sync(0xffffffffu, s, 1);
            if (!(t & 1)) s_pool[c] = s * (1.f / 16.f) + b_real[c];
        }
        __syncthreads();
        if (t < 64) {
            int c = t >> 1, p = t & 1;
            const float* w1 = car_w1 + c * CC + p * 48;
            float s = 0.f;
            #pragma unroll 8
            for (int k = 0; k < 48; k++) s += w1[k] * s_pool[p * 48 + k];
            s += __shfl_xor_sync(0xffffffffu, s, 1);
            if (!(t & 1)) s_hid[c] = fmaxf(s + car_b1[c], 0.f);
        }
        __syncthreads();
        if (t < CC) {
            float s = car_b2[t];
            const float* w2 = car_w2 + t * 32;
            #pragma unroll
            for (int j = 0; j < 32; j++) s += w2[j] * s_hid[j];
            s_ar[t] = 1.f + 1.f / (1.f + expf(-s));
        }
        __syncthreads();   // s_ar visible to all warps before epilogue

        // ---- fused dual MMA: each warp computes E and O for its tiles ----
        float acc_e[3][3][4], acc_o[3][3][4];
        #pragma unroll
        for (int mt = 0; mt < 3; mt++)
            #pragma unroll
            for (int s = 0; s < 3; s++)
                #pragma unroll
                for (int u = 0; u < 4; u++) { acc_e[mt][s][u] = 0.f; acc_o[mt][s][u] = 0.f; }

        #pragma unroll
        for (int ks = 0; ks < 12; ks++) {
            const float* xk = XW + (8 * ks + fid) * XPITCH;
            uint32_t sfr[3][2], dfr[3][2];
            #pragma unroll
            for (int s = 0; s < 3; s++) {
                if (s >= cnt) continue;
                int o1 = paddr[s] & 0xFFFF, o2 = paddr[s] >> 16;
                float a1 = xk[o1],              b1v = xk[o2];
                float a2 = xk[4 * XPITCH + o1], b2v = xk[4 * XPITCH + o2];
                sfr[s][0] = tf32r(0.5f * (a1 + b1v));
                dfr[s][0] = tf32r(0.5f * (a1 - b1v));
                sfr[s][1] = tf32r(0.5f * (a2 + b2v));
                dfr[s][1] = tf32r(0.5f * (a2 - b2v));
            }
            #pragma unroll
            for (int mt = 0; mt < 3; mt++) {
                uint4 ar4 = ((const uint4*)WrP)[((wm * 3 + mt) * 12 + ks) * 32 + lane];
                uint4 ai4 = ((const uint4*)WiP)[((wm * 3 + mt) * 12 + ks) * 32 + lane];
                #pragma unroll
                for (int s = 0; s < 3; s++) {
                    if (s >= cnt) continue;
                    mma8(acc_e[mt][s], (const uint32_t*)&ar4, sfr[s]);
                    mma8(acc_o[mt][s], (const uint32_t*)&ai4, dfr[s]);
                }
            }
        }

        // ---- in-register recombine + direct global stores ----
        #pragma unroll
        for (int mt = 0; mt < 3; mt++) {
            int cb = 16 * (wm * 3 + mt);
            int c1 = cb + g, c2 = c1 + 8;
            float ar1 = s_ar[c1], ai1 = s_ai[c1];
            float ar2 = s_ar[c2], ai2 = s_ai[c2];
            float* o1p = ob + (size_t)c1 * HW;
            float* o2p = ob + (size_t)c2 * HW;
            #pragma unroll
            for (int s = 0; s < 3; s++) {
                if (s >= cnt) continue;
                int ntg = nbase + s;
                #pragma unroll
                for (int j = 0; j < 2; j++) {
                    int r = 8 * ntg + 2 * fid + j;
                    if (r >= 130) continue;
                    int p, q; decode_rq(r, p, q);
                    int p2 = (16 - p) & 15, q2 = (16 - q) & 15;
                    size_t om  = (size_t)(h0 + p) * WWL + (w0 + q);
                    float e1 = acc_e[mt][s][j],     ov1 = acc_o[mt][s][j];
                    float e2 = acc_e[mt][s][2 + j], ov2 = acc_o[mt][s][2 + j];
                    float v1 = ar1 * e1 + ai1 * ov1;
                    float v2 = ar2 * e2 + ai2 * ov2;
                    if (r == 112) {     // window origin: IFFT of bias
                        v1 += 16.f * ar1 * b_real[c1];
                        v2 += 16.f * ar2 * b_real[c2];
                    }
                    o1p[om] = v1;
                    o2p[om] = v2;
                    if (p != p2 || q != q2) {
                        size_t omr = (size_t)(h0 + p2) * WWL + (w0 + q2);
                        o1p[omr] = ar1 * e1 - ai1 * ov1;
                        o2p[omr] = ar2 * e2 - ai2 * ov2;
                    }
                }
            }
        }
    }
}

// ---------------------------------------------------------------------------
extern "C" void kernel_launch(void* const* d_in, const int* in_sizes, int n_in,
                              void* d_out, int out_size)
{
    const float* x      = (const float*)d_in[0];
    const float* w_real = (const float*)d_in[1];
    const float* b_real = (const float*)d_in[2];
    const float* w_imag = (const float*)d_in[3];
    const float* b_imag = (const float*)d_in[4];
    const float* car_w1 = (const float*)d_in[5];
    const float* car_b1 = (const float*)d_in[6];
    const float* car_w2 = (const float*)d_in[7];
    const float* car_b2 = (const float*)d_in[8];
    const float* cai_w1 = (const float*)d_in[9];
    const float* cai_b1 = (const float*)d_in[10];
    const float* cai_w2 = (const float*)d_in[11];
    const float* cai_b2 = (const float*)d_in[12];
    float* out = (float*)d_out;

    cudaFuncSetAttribute(fused_kernel, cudaFuncAttributeMaxDynamicSharedMemorySize, SMEM_DYN);
    fused_kernel<<<GRID, NT, SMEM_DYN>>>(x, w_real, b_real, w_imag, b_imag,
                                         car_w1, car_b1, car_w2, car_b2,
                                         cai_w1, cai_b1, cai_w2, cai_b2, out);
}